// round 17
// baseline (speedup 1.0000x reference)
#include <cuda_runtime.h>
#include <cuda_bf16.h>
#include <cuda_fp16.h>
#include <cstdint>
#include <cstddef>

#define NN 50000
#define FD 128
#define NE 600000
#define MTILE 64
#define NTILES 782   // ceil(50000/64)
#define KPAD 136     // A smem row stride in bf16 units (272B: conflict-free ldmatrix)

typedef unsigned int uint32;

// ---------------- device scratch (no allocation allowed) ----------------
__device__ float g_h1[NN * FD];        // layer outputs (next-layer input)
__device__ float g_h2[NN * FD];
__device__ float g_ys[NN * FD];        // self-term y_s = h@Ws + b   (fp32)
__device__ uint32 g_yn[NN * 64];       // neigh-term y_n = h@Wn      (fp16x2, 128 cols)
__device__ float g_invdeg[NN];
__device__ int   g_count[NN];
__device__ int   g_rowstart[NN];
__device__ int   g_cursor[NN];
__device__ int   g_eidx[NE];           // CSR: src ids grouped by dst
// B weights in MMA-fragment order: [layer][ks(8)][nb(32)][lane(32)] -> (bh0,bh1,bl0,bl1)
// nb 0..15 -> Ws cols 0..127 ; nb 16..31 -> Wn cols 0..127
__device__ uint4 g_wfrag[3 * 8 * 32 * 32];
__device__ float g_biasp[3][128];

// ---------------- PTX helpers ----------------
__device__ __forceinline__ uint32 smem_u32(const void* p) {
    uint32 a;
    asm("{ .reg .u64 t; cvta.to.shared.u64 t, %1; cvt.u32.u64 %0, t; }" : "=r"(a) : "l"(p));
    return a;
}

#define LDMATRIX_X4(r0, r1, r2, r3, addr) \
    asm volatile("ldmatrix.sync.aligned.m8n8.x4.shared.b16 {%0,%1,%2,%3}, [%4];" \
        : "=r"(r0), "=r"(r1), "=r"(r2), "=r"(r3) : "r"(addr))

#define MMA_BF16(d, a, b0, b1) \
    asm volatile("mma.sync.aligned.m16n8k16.row.col.f32.bf16.bf16.f32 " \
        "{%0,%1,%2,%3}, {%4,%5,%6,%7}, {%8,%9}, {%0,%1,%2,%3};" \
        : "+f"((d)[0]), "+f"((d)[1]), "+f"((d)[2]), "+f"((d)[3]) \
        : "r"((a)[0]), "r"((a)[1]), "r"((a)[2]), "r"((a)[3]), "r"(b0), "r"(b1))

// bf16 hi/lo split of a float pair -> (hi bf16x2, lo bf16x2); low half = first elem
__device__ __forceinline__ uint2 split_pair(float v0, float v1) {
    uint32 hp, lp;
    asm("cvt.rn.bf16x2.f32 %0, %1, %2;" : "=r"(hp) : "f"(v1), "f"(v0));
    float h0 = __uint_as_float(hp << 16);
    float h1 = __uint_as_float(hp & 0xFFFF0000u);
    float r0 = v0 - h0, r1 = v1 - h1;
    asm("cvt.rn.bf16x2.f32 %0, %1, %2;" : "=r"(lp) : "f"(r1), "f"(r0));
    return make_uint2(hp, lp);
}

__device__ __forceinline__ uint32 pack_f16x2(float lo_elem, float hi_elem) {
    uint32 p;
    asm("cvt.rn.f16x2.f32 %0, %1, %2;" : "=r"(p) : "f"(hi_elem), "f"(lo_elem));
    return p;
}

// ---------------- CSR build ----------------

__global__ void zero_counts_kernel() {
    int i = blockIdx.x * blockDim.x + threadIdx.x;
    if (i < NN) g_count[i] = 0;
}

__global__ void hist_kernel(const int* __restrict__ dst) {
    int e = blockIdx.x * blockDim.x + threadIdx.x;
    if (e < NE) atomicAdd(&g_count[dst[e]], 1);
}

#define SCAN_T 1024
__global__ void __launch_bounds__(SCAN_T) scan_kernel() {
    __shared__ int s[SCAN_T];
    int tid = threadIdx.x;
    const int CH = (NN + SCAN_T - 1) / SCAN_T;
    int t0 = tid * CH;
    int t1 = t0 + CH; if (t1 > NN) t1 = NN;
    int sum = 0;
    for (int i = t0; i < t1; ++i) sum += g_count[i];
    s[tid] = sum;
    __syncthreads();
    for (int off = 1; off < SCAN_T; off <<= 1) {
        int v = (tid >= off) ? s[tid - off] : 0;
        __syncthreads();
        s[tid] += v;
        __syncthreads();
    }
    int run = s[tid] - sum;
    for (int i = t0; i < t1; ++i) {
        int c = g_count[i];
        g_rowstart[i] = run; run += c;
        g_invdeg[i] = 1.0f / fmaxf((float)c, 1.0f);
        g_cursor[i] = 0;
    }
}

__global__ void fill_kernel(const int* __restrict__ src, const int* __restrict__ dst) {
    int e = blockIdx.x * blockDim.x + threadIdx.x;
    if (e < NE) {
        int d = dst[e];
        int p = atomicAdd(&g_cursor[d], 1);
        g_eidx[g_rowstart[d] + p] = src[e];
    }
}

// ---------------- weight prep: fragment-order [Ws | Wn] along N + bias ----------------

__device__ __forceinline__ float get_w2(int layer, int k, int n,
                                        const float* Ws0, const float* Wn0,
                                        const float* Ws1, const float* Wn1,
                                        const float* Ws2, const float* Wn2) {
    if (n < 128) {
        if (layer == 0) return Ws0[k * 128 + n];
        if (layer == 1) return Ws1[k * 128 + n];
        return (n < 47) ? Ws2[k * 47 + n] : 0.f;
    }
    int m = n - 128;
    if (layer == 0) return Wn0[k * 128 + m];
    if (layer == 1) return Wn1[k * 128 + m];
    return (m < 47) ? Wn2[k * 47 + m] : 0.f;
}

__device__ __forceinline__ void split1(float v, float& hi, float& lo) {
    __nv_bfloat16 hb = __float2bfloat16_rn(v);
    hi = __bfloat162float(hb);
    lo = v - hi;
}

__device__ __forceinline__ uint32 pack_bf16x2(float lo_elem, float hi_elem) {
    uint32 p;
    asm("cvt.rn.bf16x2.f32 %0, %1, %2;" : "=r"(p) : "f"(hi_elem), "f"(lo_elem));
    return p;
}

__global__ void prep_frag_kernel(const float* __restrict__ Ws0, const float* __restrict__ Wn0, const float* __restrict__ b0,
                                 const float* __restrict__ Ws1, const float* __restrict__ Wn1, const float* __restrict__ b1,
                                 const float* __restrict__ Ws2, const float* __restrict__ Wn2, const float* __restrict__ b2) {
    int i = blockIdx.x * blockDim.x + threadIdx.x;   // 0 .. 24575
    if (i < 3 * 8 * 32 * 32) {
        int lane = i & 31;
        int nb   = (i >> 5) & 31;
        int ks   = (i >> 10) & 7;
        int layer = i >> 13;

        int n  = nb * 8 + (lane >> 2);
        int bq = (lane & 3) * 2;
        int kb = ks * 16;

        float h0, l0, h1, l1, h2, l2, h3, l3;
        split1(get_w2(layer, kb + bq,     n, Ws0, Wn0, Ws1, Wn1, Ws2, Wn2), h0, l0);
        split1(get_w2(layer, kb + bq + 1, n, Ws0, Wn0, Ws1, Wn1, Ws2, Wn2), h1, l1);
        split1(get_w2(layer, kb + bq + 8, n, Ws0, Wn0, Ws1, Wn1, Ws2, Wn2), h2, l2);
        split1(get_w2(layer, kb + bq + 9, n, Ws0, Wn0, Ws1, Wn1, Ws2, Wn2), h3, l3);

        uint4 f;
        f.x = pack_bf16x2(h0, h1);   // bh0
        f.y = pack_bf16x2(h2, h3);   // bh1
        f.z = pack_bf16x2(l0, l1);   // bl0
        f.w = pack_bf16x2(l2, l3);   // bl1
        g_wfrag[i] = f;
    }
    if (i < 3 * 128) {
        int l = i >> 7, j = i & 127;
        float bv = 0.f;
        if (l == 0) bv = b0[j];
        else if (l == 1) bv = b1[j];
        else if (j < 47) bv = b2[j];
        g_biasp[l][j] = bv;
    }
}

// ---------------- expand: y_s = h@Ws + b (fp32), y_n = h@Wn (fp16) ----------------
// 64-row tiles, K=128, N=256 ([Ws | Wn] along N). bf16 hi/lo 3-pass HMMA.
// Block: 8 warps, 2(M) x 4(N); warp tile 32x64 (8 n-blocks); mma m16n8k16.
// smem = 2 * 64 * KPAD * 2 = 34816 (< 48KB).

__global__ void __launch_bounds__(256)
expand_kernel(const float* __restrict__ h, int layer, int fout)
{
    extern __shared__ unsigned short smem[];
    unsigned short* s_ahi = smem;                 // [64][KPAD]
    unsigned short* s_alo = smem + MTILE * KPAD;

    const int tid = threadIdx.x;
    const int wid = tid >> 5;
    const int lane = tid & 31;
    const int warp_m = wid & 1;     // rows 32*warp_m .. +31
    const int warp_n = wid >> 1;    // cols 64*warp_n .. +63
    const int row0 = blockIdx.x * MTILE;

    const uint32 sa_hi = smem_u32(s_ahi);
    const uint32 sa_lo = smem_u32(s_alo);

    const int lm_l = lane & 7;
    const int lm_g = lane >> 3;
    const int lm_row = ((lm_g & 1) << 3) + lm_l;
    const int lm_kof = (lm_g & 2) << 2;

    // n-block activity (layer 2 skips cols >= fout in both halves)
    bool nt_act[8];
#pragma unroll
    for (int nt = 0; nt < 8; ++nt) {
        int nc = (warp_n * 8 + nt) * 8;
        nt_act[nt] = (nc < 128) ? (nc < fout) : ((nc - 128) < fout);
    }

    float acc[2][8][4];
#pragma unroll
    for (int mt = 0; mt < 2; ++mt)
#pragma unroll
        for (int nt = 0; nt < 8; ++nt)
#pragma unroll
            for (int c = 0; c < 4; ++c) acc[mt][nt][c] = 0.f;

    // --- A fill: 64 rows x 128 k fp32 -> bf16 hi/lo SMEM ---
#pragma unroll
    for (int it = 0; it < 8; ++it) {
        int id = tid + it * 256;
        int r = id >> 5;
        int q = id & 31;
        int row = row0 + r;
        float4 v = make_float4(0.f, 0.f, 0.f, 0.f);
        if (row < NN) v = *(const float4*)(h + (size_t)row * FD + q * 4);
        uint2 p01 = split_pair(v.x, v.y);
        uint2 p23 = split_pair(v.z, v.w);
        uint32* ph = (uint32*)(s_ahi + r * KPAD + q * 4);
        ph[0] = p01.x; ph[1] = p23.x;
        uint32* pl = (uint32*)(s_alo + r * KPAD + q * 4);
        pl[0] = p01.y; pl[1] = p23.y;
    }
    __syncthreads();

    const uint4* __restrict__ wfrag = g_wfrag + ((size_t)layer << 13);

#pragma unroll
    for (int ks = 0; ks < 8; ++ks) {
        const int k0 = ks * 16;
        uint32 ah[2][4], al[2][4];
#pragma unroll
        for (int mt = 0; mt < 2; ++mt) {
            int m = warp_m * 32 + mt * 16 + lm_row;
            uint32 off = (uint32)((m * KPAD + k0 + lm_kof) * 2);
            LDMATRIX_X4(ah[mt][0], ah[mt][1], ah[mt][2], ah[mt][3], sa_hi + off);
            LDMATRIX_X4(al[mt][0], al[mt][1], al[mt][2], al[mt][3], sa_lo + off);
        }
#pragma unroll
        for (int nt = 0; nt < 8; ++nt) {
            if (!nt_act[nt]) continue;
            int nb = warp_n * 8 + nt;
            uint4 bf = __ldg(&wfrag[((ks * 32 + nb) << 5) + lane]);
#pragma unroll
            for (int mt = 0; mt < 2; ++mt) {
                MMA_BF16(acc[mt][nt], ah[mt], bf.x, bf.y);   // hi*hi
                MMA_BF16(acc[mt][nt], al[mt], bf.x, bf.y);   // lo*hi
                MMA_BF16(acc[mt][nt], ah[mt], bf.z, bf.w);   // hi*lo
            }
        }
    }

    // --- epilogue: y_s (fp32, +bias) and y_n (fp16x2) ---
    const float* bias = g_biasp[layer];
#pragma unroll
    for (int mt = 0; mt < 2; ++mt) {
        int r_a = row0 + warp_m * 32 + mt * 16 + (lane >> 2);
        int r_b = r_a + 8;
#pragma unroll
        for (int nt = 0; nt < 8; ++nt) {
            if (!nt_act[nt]) continue;
            int j0 = warp_n * 64 + nt * 8 + (lane & 3) * 2;
            if (j0 < 128) {
                float b0v = bias[j0], b1v = bias[j0 + 1];
                if (r_a < NN) {
                    g_ys[(size_t)r_a * FD + j0]     = acc[mt][nt][0] + b0v;
                    g_ys[(size_t)r_a * FD + j0 + 1] = acc[mt][nt][1] + b1v;
                }
                if (r_b < NN) {
                    g_ys[(size_t)r_b * FD + j0]     = acc[mt][nt][2] + b0v;
                    g_ys[(size_t)r_b * FD + j0 + 1] = acc[mt][nt][3] + b1v;
                }
            } else {
                int jn = j0 - 128;           // even
                if (r_a < NN)
                    g_yn[(size_t)r_a * 64 + (jn >> 1)] = pack_f16x2(acc[mt][nt][0], acc[mt][nt][1]);
                if (r_b < NN)
                    g_yn[(size_t)r_b * 64 + (jn >> 1)] = pack_f16x2(acc[mt][nt][2], acc[mt][nt][3]);
            }
        }
    }
}

// ---------------- combine: out = act(y_s + mean(y_n[src])) ----------------
// One warp per node; lane owns 4 cols. Per edge: uint2 (4 fp16) = 256B/row total.

__global__ void __launch_bounds__(256)
combine_kernel(float* __restrict__ out, int fout, int do_relu)
{
    int node = (blockIdx.x * blockDim.x + threadIdx.x) >> 5;
    int lane = threadIdx.x & 31;
    if (node >= NN) return;
    int start = g_rowstart[node];
    int len   = g_count[node];
    float inv = g_invdeg[node];

    float a0 = 0.f, a1 = 0.f, a2 = 0.f, a3 = 0.f;
    int e = 0;
    for (; e + 4 <= len; e += 4) {
        int s0 = g_eidx[start + e];
        int s1 = g_eidx[start + e + 1];
        int s2 = g_eidx[start + e + 2];
        int s3 = g_eidx[start + e + 3];
        uint2 u0 = *(const uint2*)(g_yn + (size_t)s0 * 64 + lane * 2);
        uint2 u1 = *(const uint2*)(g_yn + (size_t)s1 * 64 + lane * 2);
        uint2 u2 = *(const uint2*)(g_yn + (size_t)s2 * 64 + lane * 2);
        uint2 u3 = *(const uint2*)(g_yn + (size_t)s3 * 64 + lane * 2);
        float2 f;
        f = __half22float2(*(const __half2*)&u0.x); a0 += f.x; a1 += f.y;
        f = __half22float2(*(const __half2*)&u0.y); a2 += f.x; a3 += f.y;
        f = __half22float2(*(const __half2*)&u1.x); a0 += f.x; a1 += f.y;
        f = __half22float2(*(const __half2*)&u1.y); a2 += f.x; a3 += f.y;
        f = __half22float2(*(const __half2*)&u2.x); a0 += f.x; a1 += f.y;
        f = __half22float2(*(const __half2*)&u2.y); a2 += f.x; a3 += f.y;
        f = __half22float2(*(const __half2*)&u3.x); a0 += f.x; a1 += f.y;
        f = __half22float2(*(const __half2*)&u3.y); a2 += f.x; a3 += f.y;
    }
    for (; e < len; ++e) {
        int s0 = g_eidx[start + e];
        uint2 u0 = *(const uint2*)(g_yn + (size_t)s0 * 64 + lane * 2);
        float2 f;
        f = __half22float2(*(const __half2*)&u0.x); a0 += f.x; a1 += f.y;
        f = __half22float2(*(const __half2*)&u0.y); a2 += f.x; a3 += f.y;
    }

    float4 ys = *(const float4*)(g_ys + (size_t)node * FD + lane * 4);
    float v0 = ys.x + a0 * inv;
    float v1 = ys.y + a1 * inv;
    float v2 = ys.z + a2 * inv;
    float v3 = ys.w + a3 * inv;
    if (do_relu) {
        v0 = fmaxf(v0, 0.f); v1 = fmaxf(v1, 0.f);
        v2 = fmaxf(v2, 0.f); v3 = fmaxf(v3, 0.f);
    }
    int j = lane * 4;
    if (fout == FD) {
        *(float4*)(out + (size_t)node * FD + j) = make_float4(v0, v1, v2, v3);
    } else {
        if (j < fout)     out[(size_t)node * fout + j]     = v0;
        if (j + 1 < fout) out[(size_t)node * fout + j + 1] = v1;
        if (j + 2 < fout) out[(size_t)node * fout + j + 2] = v2;
        if (j + 3 < fout) out[(size_t)node * fout + j + 3] = v3;
    }
}

// ---------------- launch ----------------

extern "C" void kernel_launch(void* const* d_in, const int* in_sizes, int n_in,
                              void* d_out, int out_size) {
    const float* x   = (const float*)d_in[0];
    const int*   src = (const int*)d_in[1];
    const int*   dst = (const int*)d_in[2];
    const float* Ws0 = (const float*)d_in[3];
    const float* Wn0 = (const float*)d_in[4];
    const float* b0  = (const float*)d_in[5];
    const float* Ws1 = (const float*)d_in[6];
    const float* Wn1 = (const float*)d_in[7];
    const float* b1  = (const float*)d_in[8];
    const float* Ws2 = (const float*)d_in[9];
    const float* Wn2 = (const float*)d_in[10];
    const float* b2  = (const float*)d_in[11];
    float* out = (float*)d_out;

    float *h1, *h2;
    cudaGetSymbolAddress((void**)&h1, g_h1);
    cudaGetSymbolAddress((void**)&h2, g_h2);

    const int smem_bytes = 2 * MTILE * KPAD * 2;   // 34816 < 48KB

    const int ZB = 256;
    const int node_grid    = (NN + ZB - 1) / ZB;
    const int edge_grid    = (NE + ZB - 1) / ZB;
    const int prep_grid    = (3 * 8 * 32 * 32 + ZB - 1) / ZB;
    const int combine_grid = (NN * 32 + ZB - 1) / ZB;

    // CSR build + weight prep
    zero_counts_kernel<<<node_grid, ZB>>>();
    hist_kernel<<<edge_grid, ZB>>>(dst);
    scan_kernel<<<1, SCAN_T>>>();
    fill_kernel<<<edge_grid, ZB>>>(src, dst);
    prep_frag_kernel<<<prep_grid, ZB>>>(Ws0, Wn0, b0, Ws1, Wn1, b1, Ws2, Wn2, b2);

    // layer 0
    expand_kernel<<<NTILES, 256, smem_bytes>>>(x, 0, 128);
    combine_kernel<<<combine_grid, ZB>>>(h1, 128, 1);
    // layer 1
    expand_kernel<<<NTILES, 256, smem_bytes>>>(h1, 1, 128);
    combine_kernel<<<combine_grid, ZB>>>(h2, 128, 1);
    // layer 2
    expand_kernel<<<NTILES, 256, smem_bytes>>>(h2, 2, 47);
    combine_kernel<<<combine_grid, ZB>>>(out, 47, 0);
}